// round 1
// baseline (speedup 1.0000x reference)
#include <cuda_runtime.h>
#include <stdint.h>

// Problem geometry (x: (32, 7, 512, 512) fp32; per-(B,C) slice quantile over H*W)
#define MAX_SLICES 224
#define N_PER      262144           // 512*512
#define M_SAMP     4096
#define SAMP_STRIDE (N_PER / M_SAMP)  // 64
#define CAND_MAX   16384

// Sample-window indices within the sorted 4096 samples.
// Target sample rank for q=0.01 is ~41; [8, 110) gives >10-sigma containment
// of global ranks 2621/2622. q=0.99 is the mirror image.
#define S_LO_A 8
#define S_LO_B 110
#define S_HI_A 3986
#define S_HI_B 4088

// Exact ranks / interpolation handled in select kernel via doubles.

// ---- static device scratch (no allocations allowed) ----
__device__ float    g_win[MAX_SLICES][4];              // loA, loB, hiA, hiB
__device__ unsigned g_cnt[MAX_SLICES][2];              // #elements < window lo
__device__ unsigned g_ncand[MAX_SLICES][2];
__device__ float    g_cand[MAX_SLICES][2][CAND_MAX];   // ~29 MB
__device__ float    g_q[MAX_SLICES][2];                // vmin, vmax per slice

// Monotone float <-> uint key (total order matching float compare, incl. negatives)
__device__ __forceinline__ unsigned fkey(float f) {
    unsigned u = __float_as_uint(f);
    return (u & 0x80000000u) ? ~u : (u | 0x80000000u);
}
__device__ __forceinline__ float funkey(unsigned k) {
    return (k & 0x80000000u) ? __uint_as_float(k & 0x7FFFFFFFu)
                             : __uint_as_float(~k);
}

// ============================================================
// Kernel 1: per-slice sample + bitonic sort -> candidate windows
// ============================================================
__global__ void sample_kernel(const float* __restrict__ x) {
    __shared__ float s[M_SAMP];
    int slice = blockIdx.x;
    const float* xs = x + (size_t)slice * N_PER;

    for (int i = threadIdx.x; i < M_SAMP; i += blockDim.x)
        s[i] = xs[(size_t)i * SAMP_STRIDE];
    __syncthreads();

    // Bitonic sort ascending
    for (int k = 2; k <= M_SAMP; k <<= 1) {
        for (int j = k >> 1; j > 0; j >>= 1) {
            for (int i = threadIdx.x; i < M_SAMP; i += blockDim.x) {
                int ixj = i ^ j;
                if (ixj > i) {
                    float a = s[i], b = s[ixj];
                    bool up = ((i & k) == 0);
                    if ((a > b) == up) { s[i] = b; s[ixj] = a; }
                }
            }
            __syncthreads();
        }
    }

    if (threadIdx.x == 0) {
        g_win[slice][0] = s[S_LO_A];
        g_win[slice][1] = s[S_LO_B];
        g_win[slice][2] = s[S_HI_A];
        g_win[slice][3] = s[S_HI_B];
        g_cnt[slice][0] = 0;  g_cnt[slice][1] = 0;
        g_ncand[slice][0] = 0; g_ncand[slice][1] = 0;
    }
}

// ============================================================
// Kernel 2: full pass — exact below-window counts + candidate gather
// ============================================================
__device__ __forceinline__ void wappend(int slice, int w, bool p, float v, int lane) {
    unsigned mask = __ballot_sync(0xffffffffu, p);
    if (!mask) return;
    int leader = __ffs(mask) - 1;
    unsigned base = 0;
    if (lane == leader) base = atomicAdd(&g_ncand[slice][w], (unsigned)__popc(mask));
    base = __shfl_sync(0xffffffffu, base, leader);
    if (p) {
        unsigned idx = base + (unsigned)__popc(mask & ((1u << lane) - 1u));
        if (idx < CAND_MAX) g_cand[slice][w][idx] = v;
    }
}

__global__ void count_gather_kernel(const float* __restrict__ x) {
    int slice = blockIdx.y;
    const int CHUNK = N_PER / gridDim.x;   // 16384 with 16 blocks/slice
    const float4* xs = (const float4*)(x + (size_t)slice * N_PER
                                         + (size_t)blockIdx.x * CHUNK);
    float w0 = g_win[slice][0], w1 = g_win[slice][1];
    float w2 = g_win[slice][2], w3 = g_win[slice][3];
    int lane = threadIdx.x & 31;

    unsigned cl = 0, ch = 0;
    int nvec = CHUNK / 4;
    for (int i = threadIdx.x; i < nvec; i += blockDim.x) {
        float4 v = xs[i];
        float vv[4] = {v.x, v.y, v.z, v.w};
        #pragma unroll
        for (int c = 0; c < 4; c++) {
            float f = vv[c];
            cl += (f < w0);
            ch += (f < w2);
            wappend(slice, 0, (f >= w0) && (f < w1), f, lane);
            wappend(slice, 1, (f >= w2) && (f < w3), f, lane);
        }
    }
    // warp reduce, 1 atomic per warp per counter
    #pragma unroll
    for (int o = 16; o; o >>= 1) {
        cl += __shfl_down_sync(0xffffffffu, cl, o);
        ch += __shfl_down_sync(0xffffffffu, ch, o);
    }
    if (lane == 0) {
        atomicAdd(&g_cnt[slice][0], cl);
        atomicAdd(&g_cnt[slice][1], ch);
    }
}

// ============================================================
// Kernel 3: exact radix-select among candidates (per slice, per window)
// ============================================================
__global__ void select_kernel() {
    __shared__ unsigned hist[2048];
    __shared__ unsigned tsum[256];
    __shared__ unsigned sh_digit, sh_rrem;
    __shared__ unsigned red_u[256];

    int w = blockIdx.x;       // 0 = low quantile, 1 = high quantile
    int slice = blockIdx.y;
    int tid = threadIdx.x;

    unsigned n = g_ncand[slice][w];
    if (n > CAND_MAX) n = CAND_MAX;
    unsigned cnt = g_cnt[slice][w];

    // pos = q*(N-1); K = floor(pos); frac = pos - K  (computed in double)
    double pos  = (w == 0) ? 0.01 * (double)(N_PER - 1) : 0.99 * (double)(N_PER - 1);
    long long K = (long long)pos;
    double frac = pos - (double)K;

    if (n < 2) {
        if (tid == 0) g_q[slice][w] = (n == 1) ? g_cand[slice][w][0] : 0.0f;
        return;
    }
    long long rl = K - (long long)cnt;
    if (rl < 0) rl = 0;
    if (rl > (long long)n - 2) rl = (long long)n - 2;
    int r = (int)rl;
    const float* cand = g_cand[slice][w];

    // 3-pass MSB radix select: digits of 11, 11, 10 bits
    unsigned prefix = 0, pmask = 0;
    int rrem = r;
    const int shifts[3] = {21, 10, 0};
    const int bitsv[3]  = {11, 11, 10};
    #pragma unroll
    for (int p = 0; p < 3; p++) {
        int shift = shifts[p];
        unsigned nb = 1u << bitsv[p];
        unsigned dmask = nb - 1u;
        for (int i = tid; i < 2048; i += 256) hist[i] = 0;
        __syncthreads();
        for (unsigned i = tid; i < n; i += 256) {
            unsigned u = fkey(cand[i]);
            if ((u & pmask) == prefix)
                atomicAdd(&hist[(u >> shift) & dmask], 1u);
        }
        __syncthreads();
        unsigned per = nb / 256;
        unsigned s = 0;
        for (unsigned q2 = 0; q2 < per; q2++) s += hist[tid * per + q2];
        tsum[tid] = s;
        __syncthreads();
        if (tid == 0) {
            unsigned acc = 0; int t = 0;
            for (; t < 255; t++) {
                if (acc + tsum[t] > (unsigned)rrem) break;
                acc += tsum[t];
            }
            unsigned d = (unsigned)t * per;
            for (; d < nb - 1u; d++) {
                if (acc + hist[d] > (unsigned)rrem) break;
                acc += hist[d];
            }
            sh_digit = d;
            sh_rrem  = (unsigned)rrem - acc;
        }
        __syncthreads();
        prefix |= sh_digit << shift;
        pmask  |= dmask << shift;
        rrem = (int)sh_rrem;
        __syncthreads();
    }
    unsigned v0key = prefix;

    // fixup pass: v[r+1] = v[r] if duplicates cover it, else min key > v0key
    unsigned cle = 0, mgt = 0xFFFFFFFFu;
    for (unsigned i = tid; i < n; i += 256) {
        unsigned u = fkey(cand[i]);
        cle += (u <= v0key);
        if (u > v0key && u < mgt) mgt = u;
    }
    red_u[tid] = cle; __syncthreads();
    for (int o = 128; o; o >>= 1) {
        if (tid < o) red_u[tid] += red_u[tid + o];
        __syncthreads();
    }
    unsigned cle_tot = red_u[0]; __syncthreads();
    red_u[tid] = mgt; __syncthreads();
    for (int o = 128; o; o >>= 1) {
        if (tid < o) red_u[tid] = (red_u[tid + o] < red_u[tid]) ? red_u[tid + o] : red_u[tid];
        __syncthreads();
    }
    unsigned mgt_tot = red_u[0];

    if (tid == 0) {
        unsigned v1key = (cle_tot >= (unsigned)(r + 2)) ? v0key
                       : ((mgt_tot != 0xFFFFFFFFu) ? mgt_tot : v0key);
        double v0 = (double)funkey(v0key);
        double v1 = (double)funkey(v1key);
        g_q[slice][w] = (float)(v0 + frac * (v1 - v0));
    }
}

// ============================================================
// Kernel 4: normalize + clamp (memory-bound, float4)
// ============================================================
__global__ void normalize_kernel(const float* __restrict__ x, float* __restrict__ out) {
    int slice = blockIdx.y;
    float vmin = g_q[slice][0];
    float vmax = g_q[slice][1];
    float inv = 1.0f / (vmax - vmin + 1e-8f);

    const int CHUNK = N_PER / gridDim.x;
    size_t base = (size_t)slice * N_PER + (size_t)blockIdx.x * CHUNK;
    const float4* xi = (const float4*)(x + base);
    float4* xo = (float4*)(out + base);
    int nvec = CHUNK / 4;
    for (int i = threadIdx.x; i < nvec; i += blockDim.x) {
        float4 v = xi[i];
        v.x = fminf(fmaxf((v.x - vmin) * inv, 0.0f), 1.0f);
        v.y = fminf(fmaxf((v.y - vmin) * inv, 0.0f), 1.0f);
        v.z = fminf(fmaxf((v.z - vmin) * inv, 0.0f), 1.0f);
        v.w = fminf(fmaxf((v.w - vmin) * inv, 0.0f), 1.0f);
        xo[i] = v;
    }
}

extern "C" void kernel_launch(void* const* d_in, const int* in_sizes, int n_in,
                              void* d_out, int out_size) {
    const float* x = (const float*)d_in[0];
    float* out = (float*)d_out;
    int slices = out_size / N_PER;
    if (slices > MAX_SLICES) slices = MAX_SLICES;
    if (slices < 1) return;

    sample_kernel<<<slices, 1024>>>(x);
    count_gather_kernel<<<dim3(16, slices), 256>>>(x);
    select_kernel<<<dim3(2, slices), 256>>>();
    normalize_kernel<<<dim3(32, slices), 256>>>(x, out);
}

// round 2
// speedup vs baseline: 3.2614x; 3.2614x over previous
#include <cuda_runtime.h>
#include <stdint.h>

// Problem geometry (x: (32, 7, 512, 512) fp32; per-(B,C) slice quantile over H*W)
#define MAX_SLICES 224
#define N_PER      262144           // 512*512
#define M_SAMP     4096
#define SAMP_STRIDE (N_PER / M_SAMP)  // 64
#define CAND_MAX   16384
#define SBUF       2048             // per-block staging (30-sigma vs mean 410)

// Sample-window indices within the sorted 4096 samples.
#define S_LO_A 8
#define S_LO_B 110
#define S_HI_A 3986
#define S_HI_B 4088

// ---- static device scratch (no allocations allowed) ----
__device__ float    g_win[MAX_SLICES][4];              // loA, loB, hiA, hiB
__device__ unsigned g_cnt[MAX_SLICES][2];              // #elements < window lo
__device__ unsigned g_ncand[MAX_SLICES][2];
__device__ float    g_cand[MAX_SLICES][2][CAND_MAX];   // ~29 MB
__device__ float    g_q[MAX_SLICES][2];                // vmin, vmax per slice

// Monotone float <-> uint key (total order matching float compare)
__device__ __forceinline__ unsigned fkey(float f) {
    unsigned u = __float_as_uint(f);
    return (u & 0x80000000u) ? ~u : (u | 0x80000000u);
}
__device__ __forceinline__ float funkey(unsigned k) {
    return (k & 0x80000000u) ? __uint_as_float(k & 0x7FFFFFFFu)
                             : __uint_as_float(~k);
}

// ============================================================
// Kernel 1: per-slice sample + bitonic sort -> candidate windows
// ============================================================
__global__ void sample_kernel(const float* __restrict__ x) {
    __shared__ float s[M_SAMP];
    int slice = blockIdx.x;
    const float* xs = x + (size_t)slice * N_PER;

    for (int i = threadIdx.x; i < M_SAMP; i += blockDim.x)
        s[i] = xs[(size_t)i * SAMP_STRIDE];
    __syncthreads();

    for (int k = 2; k <= M_SAMP; k <<= 1) {
        for (int j = k >> 1; j > 0; j >>= 1) {
            for (int i = threadIdx.x; i < M_SAMP; i += blockDim.x) {
                int ixj = i ^ j;
                if (ixj > i) {
                    float a = s[i], b = s[ixj];
                    bool up = ((i & k) == 0);
                    if ((a > b) == up) { s[i] = b; s[ixj] = a; }
                }
            }
            __syncthreads();
        }
    }

    if (threadIdx.x == 0) {
        g_win[slice][0] = s[S_LO_A];
        g_win[slice][1] = s[S_LO_B];
        g_win[slice][2] = s[S_HI_A];
        g_win[slice][3] = s[S_HI_B];
        g_cnt[slice][0] = 0;  g_cnt[slice][1] = 0;
        g_ncand[slice][0] = 0; g_ncand[slice][1] = 0;
    }
}

// ============================================================
// Kernel 2: full pass — below-window counts + candidate gather,
// all aggregation staged in shared memory (few global atomics/block)
// ============================================================
__global__ void count_gather_kernel(const float* __restrict__ x) {
    __shared__ float sl[SBUF];
    __shared__ float sh[SBUF];
    __shared__ unsigned s_nl, s_nh, s_cl, s_ch;
    __shared__ unsigned s_basel, s_baseh;

    int slice = blockIdx.y;
    int tid = threadIdx.x;
    if (tid == 0) { s_nl = 0; s_nh = 0; s_cl = 0; s_ch = 0; }
    __syncthreads();

    const int CHUNK = N_PER / gridDim.x;   // 16384 with 16 blocks/slice
    const float4* xs = (const float4*)(x + (size_t)slice * N_PER
                                         + (size_t)blockIdx.x * CHUNK);
    float w0 = g_win[slice][0], w1 = g_win[slice][1];
    float w2 = g_win[slice][2], w3 = g_win[slice][3];

    unsigned cl = 0, ch = 0;
    int nvec = CHUNK / 4;
    for (int i = tid; i < nvec; i += blockDim.x) {
        float4 v = xs[i];
        float vv[4] = {v.x, v.y, v.z, v.w};
        #pragma unroll
        for (int c = 0; c < 4; c++) {
            float f = vv[c];
            cl += (f < w0);
            ch += (f < w2);
            if (f >= w0 && f < w1) {              // rare (~2.5%)
                unsigned idx = atomicAdd(&s_nl, 1u);
                if (idx < SBUF) sl[idx] = f;
            }
            if (f >= w2 && f < w3) {
                unsigned idx = atomicAdd(&s_nh, 1u);
                if (idx < SBUF) sh[idx] = f;
            }
        }
    }
    // warp reduce counts, then 1 shared atomic per warp
    #pragma unroll
    for (int o = 16; o; o >>= 1) {
        cl += __shfl_down_sync(0xffffffffu, cl, o);
        ch += __shfl_down_sync(0xffffffffu, ch, o);
    }
    if ((tid & 31) == 0) {
        atomicAdd(&s_cl, cl);
        atomicAdd(&s_ch, ch);
    }
    __syncthreads();

    // single global reservation per block
    if (tid == 0) {
        unsigned nl = s_nl < SBUF ? s_nl : SBUF;
        unsigned nh = s_nh < SBUF ? s_nh : SBUF;
        s_nl = nl; s_nh = nh;
        s_basel = atomicAdd(&g_ncand[slice][0], nl);
        s_baseh = atomicAdd(&g_ncand[slice][1], nh);
        atomicAdd(&g_cnt[slice][0], s_cl);
        atomicAdd(&g_cnt[slice][1], s_ch);
    }
    __syncthreads();

    unsigned nl = s_nl, nh = s_nh, bl = s_basel, bh = s_baseh;
    for (unsigned i = tid; i < nl; i += blockDim.x) {
        unsigned gi = bl + i;
        if (gi < CAND_MAX) g_cand[slice][0][gi] = sl[i];
    }
    for (unsigned i = tid; i < nh; i += blockDim.x) {
        unsigned gi = bh + i;
        if (gi < CAND_MAX) g_cand[slice][1][gi] = sh[i];
    }
}

// ============================================================
// Kernel 3: exact radix-select among candidates (per slice, per window)
// ============================================================
__global__ void select_kernel() {
    __shared__ unsigned hist[2048];
    __shared__ unsigned tsum[256];
    __shared__ unsigned sh_digit, sh_rrem;
    __shared__ unsigned red_u[256];

    int w = blockIdx.x;       // 0 = low quantile, 1 = high quantile
    int slice = blockIdx.y;
    int tid = threadIdx.x;

    unsigned n = g_ncand[slice][w];
    if (n > CAND_MAX) n = CAND_MAX;
    unsigned cnt = g_cnt[slice][w];

    double pos  = (w == 0) ? 0.01 * (double)(N_PER - 1) : 0.99 * (double)(N_PER - 1);
    long long K = (long long)pos;
    double frac = pos - (double)K;

    if (n < 2) {
        if (tid == 0) g_q[slice][w] = (n == 1) ? g_cand[slice][w][0] : 0.0f;
        return;
    }
    long long rl = K - (long long)cnt;
    if (rl < 0) rl = 0;
    if (rl > (long long)n - 2) rl = (long long)n - 2;
    int r = (int)rl;
    const float* cand = g_cand[slice][w];

    // 3-pass MSB radix select: digits of 11, 11, 10 bits
    unsigned prefix = 0, pmask = 0;
    int rrem = r;
    const int shifts[3] = {21, 10, 0};
    const int bitsv[3]  = {11, 11, 10};
    #pragma unroll
    for (int p = 0; p < 3; p++) {
        int shift = shifts[p];
        unsigned nb = 1u << bitsv[p];
        unsigned dmask = nb - 1u;
        for (int i = tid; i < 2048; i += 256) hist[i] = 0;
        __syncthreads();
        for (unsigned i = tid; i < n; i += 256) {
            unsigned u = fkey(cand[i]);
            if ((u & pmask) == prefix)
                atomicAdd(&hist[(u >> shift) & dmask], 1u);
        }
        __syncthreads();
        unsigned per = nb / 256;
        unsigned s = 0;
        for (unsigned q2 = 0; q2 < per; q2++) s += hist[tid * per + q2];
        tsum[tid] = s;
        __syncthreads();
        if (tid == 0) {
            unsigned acc = 0; int t = 0;
            for (; t < 255; t++) {
                if (acc + tsum[t] > (unsigned)rrem) break;
                acc += tsum[t];
            }
            unsigned d = (unsigned)t * per;
            for (; d < nb - 1u; d++) {
                if (acc + hist[d] > (unsigned)rrem) break;
                acc += hist[d];
            }
            sh_digit = d;
            sh_rrem  = (unsigned)rrem - acc;
        }
        __syncthreads();
        prefix |= sh_digit << shift;
        pmask  |= dmask << shift;
        rrem = (int)sh_rrem;
        __syncthreads();
    }
    unsigned v0key = prefix;

    // fixup: v[r+1]
    unsigned cle = 0, mgt = 0xFFFFFFFFu;
    for (unsigned i = tid; i < n; i += 256) {
        unsigned u = fkey(cand[i]);
        cle += (u <= v0key);
        if (u > v0key && u < mgt) mgt = u;
    }
    red_u[tid] = cle; __syncthreads();
    for (int o = 128; o; o >>= 1) {
        if (tid < o) red_u[tid] += red_u[tid + o];
        __syncthreads();
    }
    unsigned cle_tot = red_u[0]; __syncthreads();
    red_u[tid] = mgt; __syncthreads();
    for (int o = 128; o; o >>= 1) {
        if (tid < o) red_u[tid] = (red_u[tid + o] < red_u[tid]) ? red_u[tid + o] : red_u[tid];
        __syncthreads();
    }
    unsigned mgt_tot = red_u[0];

    if (tid == 0) {
        unsigned v1key = (cle_tot >= (unsigned)(r + 2)) ? v0key
                       : ((mgt_tot != 0xFFFFFFFFu) ? mgt_tot : v0key);
        double v0 = (double)funkey(v0key);
        double v1 = (double)funkey(v1key);
        g_q[slice][w] = (float)(v0 + frac * (v1 - v0));
    }
}

// ============================================================
// Kernel 4: normalize + clamp (memory-bound, float4, FFMA.SAT)
// ============================================================
__global__ void normalize_kernel(const float* __restrict__ x, float* __restrict__ out) {
    int slice = blockIdx.y;
    float vmin = g_q[slice][0];
    float vmax = g_q[slice][1];
    float a = 1.0f / (vmax - vmin + 1e-8f);
    float b = -vmin * a;

    const int CHUNK = N_PER / gridDim.x;
    size_t base = (size_t)slice * N_PER + (size_t)blockIdx.x * CHUNK;
    const float4* xi = (const float4*)(x + base);
    float4* xo = (float4*)(out + base);
    int nvec = CHUNK / 4;
    for (int i = threadIdx.x; i < nvec; i += blockDim.x) {
        float4 v = xi[i];
        v.x = __saturatef(fmaf(v.x, a, b));
        v.y = __saturatef(fmaf(v.y, a, b));
        v.z = __saturatef(fmaf(v.z, a, b));
        v.w = __saturatef(fmaf(v.w, a, b));
        xo[i] = v;
    }
}

extern "C" void kernel_launch(void* const* d_in, const int* in_sizes, int n_in,
                              void* d_out, int out_size) {
    const float* x = (const float*)d_in[0];
    float* out = (float*)d_out;
    int slices = out_size / N_PER;
    if (slices > MAX_SLICES) slices = MAX_SLICES;
    if (slices < 1) return;

    sample_kernel<<<slices, 1024>>>(x);
    count_gather_kernel<<<dim3(16, slices), 256>>>(x);
    select_kernel<<<dim3(2, slices), 256>>>();
    normalize_kernel<<<dim3(32, slices), 256>>>(x, out);
}

// round 3
// speedup vs baseline: 3.6788x; 1.1280x over previous
#include <cuda_runtime.h>
#include <stdint.h>

// Problem geometry (x: (32, 7, 512, 512) fp32; per-(B,C) slice quantile over H*W)
#define MAX_SLICES 224
#define N_PER      262144           // 512*512
#define M_SAMP     4096
#define SAMP_STRIDE (N_PER / M_SAMP)  // 64
#define CAND_MAX   32768
#define SBUF       3072             // per-block staging

// Sample-rank brackets (0-indexed, among 4096 sorted samples).
// Global rank 2621 (q=0.01) has sample-rank mean 40.96, sigma 6.37:
// [2, 140] is a >5.8-sigma / >15-sigma bracket. Mirror for q=0.99.
#define S_LO_A 2
#define S_LO_B 140
#define S_HI_A 3955
#define S_HI_B 4093

#define NBIN 4096                   // top-12 bits of monotone key

// ---- static device scratch (no allocations allowed) ----
__device__ float    g_win[MAX_SLICES][4];              // lo0, hi0, lo1, hi1
__device__ unsigned g_cnt[MAX_SLICES][2];              // #elements < window lo
__device__ unsigned g_ncand[MAX_SLICES][2];
__device__ float    g_cand[MAX_SLICES][2][CAND_MAX];   // ~58 MB
__device__ float    g_q[MAX_SLICES][2];                // vmin, vmax per slice

// Monotone float <-> uint key (total order matching float compare)
__device__ __forceinline__ unsigned fkey(float f) {
    unsigned u = __float_as_uint(f);
    return (u & 0x80000000u) ? ~u : (u | 0x80000000u);
}
__device__ __forceinline__ float funkey(unsigned k) {
    return (k & 0x80000000u) ? __uint_as_float(k & 0x7FFFFFFFu)
                             : __uint_as_float(~k);
}

// ============================================================
// Kernel 1: per-slice sample histogram -> conservative windows
// (no sort: bin edges of the bins holding bracket sample-ranks)
// ============================================================
__global__ void sample_kernel(const float* __restrict__ x) {
    __shared__ unsigned hist[NBIN];
    __shared__ unsigned tsum[256];      // per-thread partial (16 bins each)
    __shared__ unsigned toff[256];      // exclusive prefix over tsum
    __shared__ unsigned sh_bin[4];

    int slice = blockIdx.x;
    int tid = threadIdx.x;
    const float* xs = x + (size_t)slice * N_PER;

    for (int i = tid; i < NBIN; i += 256) hist[i] = 0;
    __syncthreads();

    for (int i = tid; i < M_SAMP; i += 256) {
        float f = xs[(size_t)i * SAMP_STRIDE];
        atomicAdd(&hist[fkey(f) >> 20], 1u);
    }
    __syncthreads();

    // per-thread sum of its 16 contiguous bins
    unsigned s = 0;
    #pragma unroll
    for (int b = 0; b < 16; b++) s += hist[tid * 16 + b];
    tsum[tid] = s;
    __syncthreads();
    if (tid == 0) {
        unsigned acc = 0;
        for (int t = 0; t < 256; t++) { toff[t] = acc; acc += tsum[t]; }
    }
    __syncthreads();

    // For each target sample-rank R: bin = first bin with cum > R.
    const int ranks[4] = {S_LO_A, S_LO_B, S_HI_A, S_HI_B};
    for (int q = tid; q < 4; q += 256) {
        unsigned R = (unsigned)ranks[q];
        // find thread-chunk: last t with toff[t] <= R
        int t = 0;
        for (int j = 0; j < 256; j++) if (toff[j] <= R) t = j;  // small; fine
        unsigned acc = toff[t];
        int bin = t * 16;
        for (int b = 0; b < 16; b++) {
            if (acc + hist[t * 16 + b] > R) { bin = t * 16 + b; break; }
            acc += hist[t * 16 + b];
        }
        sh_bin[q] = (unsigned)bin;
    }
    __syncthreads();

    if (tid == 0) {
        // window 0 (low quantile): [lo-edge(bin[0]), lo-edge(bin[1]+1))
        g_win[slice][0] = funkey(sh_bin[0] << 20);
        g_win[slice][1] = funkey((sh_bin[1] + 1u) << 20);
        g_win[slice][2] = funkey(sh_bin[2] << 20);
        g_win[slice][3] = funkey((sh_bin[3] + 1u) << 20);
        g_cnt[slice][0] = 0;  g_cnt[slice][1] = 0;
        g_ncand[slice][0] = 0; g_ncand[slice][1] = 0;
    }
}

// ============================================================
// Kernel 2: full pass — below-window counts + candidate gather,
// all aggregation staged in shared memory
// ============================================================
__global__ void count_gather_kernel(const float* __restrict__ x) {
    __shared__ float sl[SBUF];
    __shared__ float sh[SBUF];
    __shared__ unsigned s_nl, s_nh, s_cl, s_ch;
    __shared__ unsigned s_basel, s_baseh;

    int slice = blockIdx.y;
    int tid = threadIdx.x;
    if (tid == 0) { s_nl = 0; s_nh = 0; s_cl = 0; s_ch = 0; }
    __syncthreads();

    const int CHUNK = N_PER / gridDim.x;   // 16384 with 16 blocks/slice
    const float4* xs = (const float4*)(x + (size_t)slice * N_PER
                                         + (size_t)blockIdx.x * CHUNK);
    float w0 = g_win[slice][0], w1 = g_win[slice][1];
    float w2 = g_win[slice][2], w3 = g_win[slice][3];

    unsigned cl = 0, ch = 0;
    int nvec = CHUNK / 4;
    for (int i = tid; i < nvec; i += blockDim.x) {
        float4 v = xs[i];
        float vv[4] = {v.x, v.y, v.z, v.w};
        #pragma unroll
        for (int c = 0; c < 4; c++) {
            float f = vv[c];
            cl += (f < w0);
            ch += (f < w2);
            if (f >= w0 && f < w1) {              // rare (~5%)
                unsigned idx = atomicAdd(&s_nl, 1u);
                if (idx < SBUF) sl[idx] = f;
            }
            if (f >= w2 && f < w3) {
                unsigned idx = atomicAdd(&s_nh, 1u);
                if (idx < SBUF) sh[idx] = f;
            }
        }
    }
    #pragma unroll
    for (int o = 16; o; o >>= 1) {
        cl += __shfl_down_sync(0xffffffffu, cl, o);
        ch += __shfl_down_sync(0xffffffffu, ch, o);
    }
    if ((tid & 31) == 0) {
        atomicAdd(&s_cl, cl);
        atomicAdd(&s_ch, ch);
    }
    __syncthreads();

    if (tid == 0) {
        unsigned nl = s_nl < SBUF ? s_nl : SBUF;
        unsigned nh = s_nh < SBUF ? s_nh : SBUF;
        s_nl = nl; s_nh = nh;
        s_basel = atomicAdd(&g_ncand[slice][0], nl);
        s_baseh = atomicAdd(&g_ncand[slice][1], nh);
        atomicAdd(&g_cnt[slice][0], s_cl);
        atomicAdd(&g_cnt[slice][1], s_ch);
    }
    __syncthreads();

    unsigned nl = s_nl, nh = s_nh, bl = s_basel, bh = s_baseh;
    for (unsigned i = tid; i < nl; i += blockDim.x) {
        unsigned gi = bl + i;
        if (gi < CAND_MAX) g_cand[slice][0][gi] = sl[i];
    }
    for (unsigned i = tid; i < nh; i += blockDim.x) {
        unsigned gi = bh + i;
        if (gi < CAND_MAX) g_cand[slice][1][gi] = sh[i];
    }
}

// ============================================================
// Kernel 3: exact radix-select among candidates (per slice, per window)
// ============================================================
__global__ void select_kernel() {
    __shared__ unsigned hist[2048];
    __shared__ unsigned tsum[256];
    __shared__ unsigned sh_digit, sh_rrem;
    __shared__ unsigned red_u[256];

    int w = blockIdx.x;       // 0 = low quantile, 1 = high quantile
    int slice = blockIdx.y;
    int tid = threadIdx.x;

    unsigned n = g_ncand[slice][w];
    if (n > CAND_MAX) n = CAND_MAX;
    unsigned cnt = g_cnt[slice][w];

    double pos  = (w == 0) ? 0.01 * (double)(N_PER - 1) : 0.99 * (double)(N_PER - 1);
    long long K = (long long)pos;
    double frac = pos - (double)K;

    if (n < 2) {
        if (tid == 0) g_q[slice][w] = (n == 1) ? g_cand[slice][w][0] : 0.0f;
        return;
    }
    long long rl = K - (long long)cnt;
    if (rl < 0) rl = 0;
    if (rl > (long long)n - 2) rl = (long long)n - 2;
    int r = (int)rl;
    const float* cand = g_cand[slice][w];

    // 3-pass MSB radix select: digits of 11, 11, 10 bits
    unsigned prefix = 0, pmask = 0;
    int rrem = r;
    const int shifts[3] = {21, 10, 0};
    const int bitsv[3]  = {11, 11, 10};
    #pragma unroll
    for (int p = 0; p < 3; p++) {
        int shift = shifts[p];
        unsigned nb = 1u << bitsv[p];
        unsigned dmask = nb - 1u;
        for (int i = tid; i < 2048; i += 256) hist[i] = 0;
        __syncthreads();
        for (unsigned i = tid; i < n; i += 256) {
            unsigned u = fkey(cand[i]);
            if ((u & pmask) == prefix)
                atomicAdd(&hist[(u >> shift) & dmask], 1u);
        }
        __syncthreads();
        unsigned per = nb / 256;
        unsigned s = 0;
        for (unsigned q2 = 0; q2 < per; q2++) s += hist[tid * per + q2];
        tsum[tid] = s;
        __syncthreads();
        if (tid == 0) {
            unsigned acc = 0; int t = 0;
            for (; t < 255; t++) {
                if (acc + tsum[t] > (unsigned)rrem) break;
                acc += tsum[t];
            }
            unsigned d = (unsigned)t * per;
            for (; d < nb - 1u; d++) {
                if (acc + hist[d] > (unsigned)rrem) break;
                acc += hist[d];
            }
            sh_digit = d;
            sh_rrem  = (unsigned)rrem - acc;
        }
        __syncthreads();
        prefix |= sh_digit << shift;
        pmask  |= dmask << shift;
        rrem = (int)sh_rrem;
        __syncthreads();
    }
    unsigned v0key = prefix;

    // fixup: v[r+1]
    unsigned cle = 0, mgt = 0xFFFFFFFFu;
    for (unsigned i = tid; i < n; i += 256) {
        unsigned u = fkey(cand[i]);
        cle += (u <= v0key);
        if (u > v0key && u < mgt) mgt = u;
    }
    red_u[tid] = cle; __syncthreads();
    for (int o = 128; o; o >>= 1) {
        if (tid < o) red_u[tid] += red_u[tid + o];
        __syncthreads();
    }
    unsigned cle_tot = red_u[0]; __syncthreads();
    red_u[tid] = mgt; __syncthreads();
    for (int o = 128; o; o >>= 1) {
        if (tid < o) red_u[tid] = (red_u[tid + o] < red_u[tid]) ? red_u[tid + o] : red_u[tid];
        __syncthreads();
    }
    unsigned mgt_tot = red_u[0];

    if (tid == 0) {
        unsigned v1key = (cle_tot >= (unsigned)(r + 2)) ? v0key
                       : ((mgt_tot != 0xFFFFFFFFu) ? mgt_tot : v0key);
        double v0 = (double)funkey(v0key);
        double v1 = (double)funkey(v1key);
        g_q[slice][w] = (float)(v0 + frac * (v1 - v0));
    }
}

// ============================================================
// Kernel 4: normalize + clamp (memory-bound, float4, FFMA.SAT)
// ============================================================
__global__ void normalize_kernel(const float* __restrict__ x, float* __restrict__ out) {
    int slice = blockIdx.y;
    float vmin = g_q[slice][0];
    float vmax = g_q[slice][1];
    float a = 1.0f / (vmax - vmin + 1e-8f);
    float b = -vmin * a;

    const int CHUNK = N_PER / gridDim.x;
    size_t base = (size_t)slice * N_PER + (size_t)blockIdx.x * CHUNK;
    const float4* xi = (const float4*)(x + base);
    float4* xo = (float4*)(out + base);
    int nvec = CHUNK / 4;
    for (int i = threadIdx.x; i < nvec; i += blockDim.x) {
        float4 v = xi[i];
        v.x = __saturatef(fmaf(v.x, a, b));
        v.y = __saturatef(fmaf(v.y, a, b));
        v.z = __saturatef(fmaf(v.z, a, b));
        v.w = __saturatef(fmaf(v.w, a, b));
        xo[i] = v;
    }
}

extern "C" void kernel_launch(void* const* d_in, const int* in_sizes, int n_in,
                              void* d_out, int out_size) {
    const float* x = (const float*)d_in[0];
    float* out = (float*)d_out;
    int slices = out_size / N_PER;
    if (slices > MAX_SLICES) slices = MAX_SLICES;
    if (slices < 1) return;

    sample_kernel<<<slices, 256>>>(x);
    count_gather_kernel<<<dim3(16, slices), 256>>>(x);
    select_kernel<<<dim3(2, slices), 256>>>();
    normalize_kernel<<<dim3(32, slices), 256>>>(x, out);
}

// round 4
// speedup vs baseline: 3.9793x; 1.0817x over previous
#include <cuda_runtime.h>
#include <stdint.h>

// Problem geometry (x: (32, 7, 512, 512) fp32; per-(B,C) slice quantile over H*W)
#define MAX_SLICES 224
#define N_PER      262144           // 512*512
#define M_SAMP     4096
#define SAMP_STRIDE (N_PER / M_SAMP)  // 64
#define CAND_MAX   32768

// Sample-rank brackets (0-indexed, among 4096 sorted samples).
#define S_LO_A 2
#define S_LO_B 140
#define S_HI_A 3955
#define S_HI_B 4093

#define NBIN 4096                   // top-12 bits of monotone key

// gather config
#define GBLK  32                    // blocks per slice
#define GCHUNK (N_PER / GBLK)       // 8192 elements
#define STASH 16                    // per-thread candidate stash (mean ~1.1)
#define OVF   256                   // per-block overflow fallback

// ---- static device scratch (no allocations allowed) ----
__device__ float    g_win[MAX_SLICES][4];              // lo0, hi0, lo1, hi1
__device__ unsigned g_cnt[MAX_SLICES][2];              // #elements < window lo
__device__ unsigned g_ncand[MAX_SLICES][2];
__device__ float    g_cand[MAX_SLICES][2][CAND_MAX];   // ~58 MB
__device__ float    g_q[MAX_SLICES][2];                // vmin, vmax per slice

// Monotone float <-> uint key (total order matching float compare)
__device__ __forceinline__ unsigned fkey(float f) {
    unsigned u = __float_as_uint(f);
    return (u & 0x80000000u) ? ~u : (u | 0x80000000u);
}
__device__ __forceinline__ float funkey(unsigned k) {
    return (k & 0x80000000u) ? __uint_as_float(k & 0x7FFFFFFFu)
                             : __uint_as_float(~k);
}

// ============================================================
// Kernel 1: per-slice sample histogram -> conservative windows
// ============================================================
__global__ void sample_kernel(const float* __restrict__ x) {
    __shared__ unsigned hist[NBIN];
    __shared__ unsigned toff[257];      // exclusive prefix over 256 chunk sums
    __shared__ unsigned sh_bin[4];

    int slice = blockIdx.x;
    int tid = threadIdx.x;
    const float* xs = x + (size_t)slice * N_PER;

    for (int i = tid; i < NBIN; i += 256) hist[i] = 0;
    __syncthreads();

    for (int i = tid; i < M_SAMP; i += 256) {
        float f = xs[(size_t)i * SAMP_STRIDE];
        atomicAdd(&hist[fkey(f) >> 20], 1u);
    }
    __syncthreads();

    // per-thread sum of 16 contiguous bins
    unsigned s = 0;
    #pragma unroll
    for (int b = 0; b < 16; b++) s += hist[tid * 16 + b];

    // block exclusive scan of the 256 sums (warp shfl + 8-entry serial)
    __shared__ unsigned wsum[8];
    int lane = tid & 31, wrp = tid >> 5;
    unsigned cum = s;
    #pragma unroll
    for (int o = 1; o < 32; o <<= 1) {
        unsigned t = __shfl_up_sync(0xffffffffu, cum, o);
        if (lane >= o) cum += t;
    }
    if (lane == 31) wsum[wrp] = cum;
    __syncthreads();
    if (tid == 0) {
        unsigned acc = 0;
        #pragma unroll
        for (int w = 0; w < 8; w++) { unsigned t = wsum[w]; wsum[w] = acc; acc += t; }
    }
    __syncthreads();
    toff[tid] = wsum[wrp] + cum - s;     // exclusive prefix
    if (tid == 255) toff[256] = M_SAMP;
    __syncthreads();

    // rank -> bin via binary search over toff, then 16-bin scan
    const int ranks[4] = {S_LO_A, S_LO_B, S_HI_A, S_HI_B};
    if (tid < 4) {
        unsigned R = (unsigned)ranks[tid];
        int lo = 0, hi = 256;                    // find last t with toff[t] <= R
        while (hi - lo > 1) {
            int mid = (lo + hi) >> 1;
            if (toff[mid] <= R) lo = mid; else hi = mid;
        }
        unsigned acc = toff[lo];
        int bin = lo * 16;
        #pragma unroll
        for (int b = 0; b < 16; b++) {
            unsigned h = hist[lo * 16 + b];
            if (acc + h > R) { bin = lo * 16 + b; break; }
            acc += h;
        }
        sh_bin[tid] = (unsigned)bin;
    }
    __syncthreads();

    if (tid == 0) {
        g_win[slice][0] = funkey(sh_bin[0] << 20);
        g_win[slice][1] = funkey((sh_bin[1] + 1u) << 20);
        g_win[slice][2] = funkey(sh_bin[2] << 20);
        g_win[slice][3] = funkey((sh_bin[3] + 1u) << 20);
        g_cnt[slice][0] = 0;  g_cnt[slice][1] = 0;
        g_ncand[slice][0] = 0; g_ncand[slice][1] = 0;
    }
}

// ============================================================
// Kernel 2: full pass — counts + candidate gather via private
// per-thread SMEM stashes (no per-element atomics), block scan,
// one global reservation per block.
// ============================================================
__global__ void count_gather_kernel(const float* __restrict__ x) {
    __shared__ float stL[256][STASH + 1];   // +1 pad: conflict-free
    __shared__ float stH[256][STASH + 1];
    __shared__ float ovfL[OVF], ovfH[OVF];
    __shared__ unsigned s_ovl, s_ovh, s_cl, s_ch;
    __shared__ unsigned s_basel, s_baseh, s_totl, s_toth;
    __shared__ unsigned wsumL[8], wsumH[8];

    int slice = blockIdx.y;
    int tid = threadIdx.x;
    int lane = tid & 31, wrp = tid >> 5;
    if (tid == 0) { s_ovl = 0; s_ovh = 0; s_cl = 0; s_ch = 0; }
    __syncthreads();

    const float4* xs = (const float4*)(x + (size_t)slice * N_PER
                                         + (size_t)blockIdx.x * GCHUNK);
    float w0 = g_win[slice][0], w1 = g_win[slice][1];
    float w2 = g_win[slice][2], w3 = g_win[slice][3];

    unsigned cl = 0, ch = 0, nl = 0, nh = 0;
    const int NV = GCHUNK / 4;          // 2048 float4
    #pragma unroll 4
    for (int i = tid; i < NV; i += 256) {
        float4 v = xs[i];
        float vv[4] = {v.x, v.y, v.z, v.w};
        #pragma unroll
        for (int c = 0; c < 4; c++) {
            float f = vv[c];
            bool b0 = (f < w0), b2 = (f < w2);
            cl += b0; ch += b2;
            if (!b0 && f < w1) {                       // low window (~3.5%)
                if (nl < STASH) stL[tid][nl] = f;
                else { unsigned o = atomicAdd(&s_ovl, 1u); if (o < OVF) ovfL[o] = f; }
                nl++;
            }
            if (!b2 && f < w3) {                       // high window
                if (nh < STASH) stH[tid][nh] = f;
                else { unsigned o = atomicAdd(&s_ovh, 1u); if (o < OVF) ovfH[o] = f; }
                nh++;
            }
        }
    }
    if (nl > STASH) nl = STASH;
    if (nh > STASH) nh = STASH;

    // counts: warp reduce, one shared atomic per warp
    #pragma unroll
    for (int o = 16; o; o >>= 1) {
        cl += __shfl_down_sync(0xffffffffu, cl, o);
        ch += __shfl_down_sync(0xffffffffu, ch, o);
    }
    if (lane == 0) { atomicAdd(&s_cl, cl); atomicAdd(&s_ch, ch); }

    // block exclusive scan of stash counts (both arrays via shfl)
    unsigned cumL = nl, cumH = nh;
    #pragma unroll
    for (int o = 1; o < 32; o <<= 1) {
        unsigned tL = __shfl_up_sync(0xffffffffu, cumL, o);
        unsigned tH = __shfl_up_sync(0xffffffffu, cumH, o);
        if (lane >= o) { cumL += tL; cumH += tH; }
    }
    if (lane == 31) { wsumL[wrp] = cumL; wsumH[wrp] = cumH; }
    __syncthreads();

    if (tid == 0) {
        unsigned aL = 0, aH = 0;
        #pragma unroll
        for (int w = 0; w < 8; w++) {
            unsigned tL = wsumL[w], tH = wsumH[w];
            wsumL[w] = aL; wsumH[w] = aH;
            aL += tL; aH += tH;
        }
        unsigned ovl = s_ovl < OVF ? s_ovl : OVF;
        unsigned ovh = s_ovh < OVF ? s_ovh : OVF;
        s_ovl = ovl; s_ovh = ovh;
        s_totl = aL; s_toth = aH;
        s_basel = atomicAdd(&g_ncand[slice][0], aL + ovl);
        s_baseh = atomicAdd(&g_ncand[slice][1], aH + ovh);
        atomicAdd(&g_cnt[slice][0], s_cl);
        atomicAdd(&g_cnt[slice][1], s_ch);
    }
    __syncthreads();

    unsigned offL = s_basel + wsumL[wrp] + cumL - nl;
    unsigned offH = s_baseh + wsumH[wrp] + cumH - nh;
    for (unsigned j = 0; j < nl; j++) {
        unsigned gi = offL + j;
        if (gi < CAND_MAX) g_cand[slice][0][gi] = stL[tid][j];
    }
    for (unsigned j = 0; j < nh; j++) {
        unsigned gi = offH + j;
        if (gi < CAND_MAX) g_cand[slice][1][gi] = stH[tid][j];
    }
    // overflow spill (rare)
    for (unsigned j = tid; j < s_ovl; j += 256) {
        unsigned gi = s_basel + s_totl + j;
        if (gi < CAND_MAX) g_cand[slice][0][gi] = ovfL[j];
    }
    for (unsigned j = tid; j < s_ovh; j += 256) {
        unsigned gi = s_baseh + s_toth + j;
        if (gi < CAND_MAX) g_cand[slice][1][gi] = ovfH[j];
    }
}

// ============================================================
// Kernel 3: exact radix-select among candidates
// (digit-find parallelized: warp shfl scan + ballot)
// ============================================================
__global__ void select_kernel() {
    __shared__ unsigned hist[2048];
    __shared__ unsigned tsum[256];
    __shared__ unsigned sh_digit, sh_rrem;
    __shared__ unsigned red_u[256];

    int w = blockIdx.x;
    int slice = blockIdx.y;
    int tid = threadIdx.x;

    unsigned n = g_ncand[slice][w];
    if (n > CAND_MAX) n = CAND_MAX;
    unsigned cnt = g_cnt[slice][w];

    double pos  = (w == 0) ? 0.01 * (double)(N_PER - 1) : 0.99 * (double)(N_PER - 1);
    long long K = (long long)pos;
    double frac = pos - (double)K;

    if (n < 2) {
        if (tid == 0) g_q[slice][w] = (n == 1) ? g_cand[slice][w][0] : 0.0f;
        return;
    }
    long long rl = K - (long long)cnt;
    if (rl < 0) rl = 0;
    if (rl > (long long)n - 2) rl = (long long)n - 2;
    int r = (int)rl;
    const float* cand = g_cand[slice][w];

    unsigned prefix = 0, pmask = 0;
    int rrem = r;
    const int shifts[3] = {21, 10, 0};
    const int bitsv[3]  = {11, 11, 10};
    #pragma unroll
    for (int p = 0; p < 3; p++) {
        int shift = shifts[p];
        unsigned nb = 1u << bitsv[p];
        unsigned dmask = nb - 1u;
        unsigned per = nb / 256;              // 8, 8, 4
        for (int i = tid; i < 2048; i += 256) hist[i] = 0;
        __syncthreads();
        for (unsigned i = tid; i < n; i += 256) {
            unsigned u = fkey(cand[i]);
            if ((u & pmask) == prefix)
                atomicAdd(&hist[(u >> shift) & dmask], 1u);
        }
        __syncthreads();
        unsigned s = 0;
        for (unsigned q2 = 0; q2 < per; q2++) s += hist[tid * per + q2];
        tsum[tid] = s;
        __syncthreads();

        // warp0: find chunk/digit containing rank rrem via shfl scan + ballot
        if (tid < 32) {
            unsigned part[8];
            unsigned ls = 0;
            #pragma unroll
            for (int j = 0; j < 8; j++) { part[j] = tsum[tid * 8 + j]; ls += part[j]; }
            unsigned cum = ls;
            #pragma unroll
            for (int o = 1; o < 32; o <<= 1) {
                unsigned t = __shfl_up_sync(0xffffffffu, cum, o);
                if (tid >= o) cum += t;
            }
            unsigned excl = cum - ls;
            unsigned ball = __ballot_sync(0xffffffffu, cum > (unsigned)rrem);
            int cross = __ffs(ball) - 1;          // guaranteed >= 0 (rrem < n)
            if (tid == cross) {
                unsigned acc = excl;
                int tc = tid * 8;                 // thread-chunk index
                #pragma unroll
                for (int j = 0; j < 8; j++) {
                    if (acc + part[j] > (unsigned)rrem) { tc = tid * 8 + j; break; }
                    acc += part[j];
                }
                // scan the `per` bins of chunk tc
                unsigned d = (unsigned)tc * per;
                for (unsigned b = 0; b < per; b++) {
                    unsigned h = hist[tc * per + b];
                    if (acc + h > (unsigned)rrem) { d = (unsigned)tc * per + b; break; }
                    acc += h;
                }
                sh_digit = d;
                sh_rrem = (unsigned)rrem - acc;
            }
        }
        __syncthreads();
        prefix |= sh_digit << shift;
        pmask  |= dmask << shift;
        rrem = (int)sh_rrem;
        __syncthreads();
    }
    unsigned v0key = prefix;

    // fixup: v[r+1]
    unsigned cle = 0, mgt = 0xFFFFFFFFu;
    for (unsigned i = tid; i < n; i += 256) {
        unsigned u = fkey(cand[i]);
        cle += (u <= v0key);
        if (u > v0key && u < mgt) mgt = u;
    }
    red_u[tid] = cle; __syncthreads();
    for (int o = 128; o; o >>= 1) {
        if (tid < o) red_u[tid] += red_u[tid + o];
        __syncthreads();
    }
    unsigned cle_tot = red_u[0]; __syncthreads();
    red_u[tid] = mgt; __syncthreads();
    for (int o = 128; o; o >>= 1) {
        if (tid < o) red_u[tid] = (red_u[tid + o] < red_u[tid]) ? red_u[tid + o] : red_u[tid];
        __syncthreads();
    }
    unsigned mgt_tot = red_u[0];

    if (tid == 0) {
        unsigned v1key = (cle_tot >= (unsigned)(r + 2)) ? v0key
                       : ((mgt_tot != 0xFFFFFFFFu) ? mgt_tot : v0key);
        double v0 = (double)funkey(v0key);
        double v1 = (double)funkey(v1key);
        g_q[slice][w] = (float)(v0 + frac * (v1 - v0));
    }
}

// ============================================================
// Kernel 4: normalize + clamp (memory-bound, float4, FFMA.SAT)
// ============================================================
__global__ void normalize_kernel(const float* __restrict__ x, float* __restrict__ out) {
    int slice = blockIdx.y;
    float vmin = g_q[slice][0];
    float vmax = g_q[slice][1];
    float a = 1.0f / (vmax - vmin + 1e-8f);
    float b = -vmin * a;

    const int CHUNK = N_PER / gridDim.x;
    size_t base = (size_t)slice * N_PER + (size_t)blockIdx.x * CHUNK;
    const float4* xi = (const float4*)(x + base);
    float4* xo = (float4*)(out + base);
    int nvec = CHUNK / 4;
    for (int i = threadIdx.x; i < nvec; i += blockDim.x) {
        float4 v = xi[i];
        v.x = __saturatef(fmaf(v.x, a, b));
        v.y = __saturatef(fmaf(v.y, a, b));
        v.z = __saturatef(fmaf(v.z, a, b));
        v.w = __saturatef(fmaf(v.w, a, b));
        xo[i] = v;
    }
}

extern "C" void kernel_launch(void* const* d_in, const int* in_sizes, int n_in,
                              void* d_out, int out_size) {
    const float* x = (const float*)d_in[0];
    float* out = (float*)d_out;
    int slices = out_size / N_PER;
    if (slices > MAX_SLICES) slices = MAX_SLICES;
    if (slices < 1) return;

    sample_kernel<<<slices, 256>>>(x);
    count_gather_kernel<<<dim3(GBLK, slices), 256>>>(x);
    select_kernel<<<dim3(2, slices), 256>>>();
    normalize_kernel<<<dim3(32, slices), 256>>>(x, out);
}

// round 5
// speedup vs baseline: 4.3215x; 1.0860x over previous
#include <cuda_runtime.h>
#include <stdint.h>

// Problem geometry (x: (32, 7, 512, 512) fp32; per-(B,C) slice quantile over H*W)
#define MAX_SLICES 224
#define N_PER      262144           // 512*512
#define M_SAMP     4096
#define SAMP_STRIDE (N_PER / M_SAMP)  // 64
#define CAND_MAX   32768

// Sample-rank brackets (0-indexed, among 4096 sorted samples).
#define S_LO_A 2
#define S_LO_B 140
#define S_HI_A 3955
#define S_HI_B 4093

#define NBIN 4096                   // top-12 bits of monotone key

// work partition
#define GBLK   32                   // gather blocks per slice
#define GCHUNK (N_PER / GBLK)       // 8192 elements
#define NBLKN  32                   // normalize blocks per slice
#define NCHUNK (N_PER / NBLKN)      // 8192 elements
#define STASH  8                    // per-thread candidate stash (mean ~1.1)
#define SROW   (STASH + 1)          // padded row, conflict-free
#define OVF    256                  // per-block overflow fallback

// ---- static device scratch (no allocations allowed) ----
__device__ float    g_win[MAX_SLICES][4];
__device__ unsigned g_cnt[MAX_SLICES][2];
__device__ unsigned g_ncand[MAX_SLICES][2];
__device__ float    g_cand[MAX_SLICES][2][CAND_MAX];
__device__ float    g_q[MAX_SLICES][2];
__device__ unsigned g_ticket;
__device__ unsigned g_done[MAX_SLICES];
__device__ unsigned g_flag[MAX_SLICES];

// Monotone float <-> uint key
__device__ __forceinline__ unsigned fkey(float f) {
    unsigned u = __float_as_uint(f);
    return (u & 0x80000000u) ? ~u : (u | 0x80000000u);
}
__device__ __forceinline__ float funkey(unsigned k) {
    return (k & 0x80000000u) ? __uint_as_float(k & 0x7FFFFFFFu)
                             : __uint_as_float(~k);
}

// ============================================================
// Kernel 1: per-slice sample histogram -> conservative windows
// + reset of all cross-kernel state (graph-replay safe)
// ============================================================
__global__ void sample_kernel(const float* __restrict__ x) {
    __shared__ unsigned hist[NBIN];
    __shared__ unsigned toff[257];
    __shared__ unsigned sh_bin[4];
    __shared__ unsigned wsum[8];

    int slice = blockIdx.x;
    int tid = threadIdx.x;
    const float* xs = x + (size_t)slice * N_PER;

    if (slice == 0 && tid == 0) g_ticket = 0;

    for (int i = tid; i < NBIN; i += 256) hist[i] = 0;
    __syncthreads();

    for (int i = tid; i < M_SAMP; i += 256) {
        float f = xs[(size_t)i * SAMP_STRIDE];
        atomicAdd(&hist[fkey(f) >> 20], 1u);
    }
    __syncthreads();

    unsigned s = 0;
    #pragma unroll
    for (int b = 0; b < 16; b++) s += hist[tid * 16 + b];

    int lane = tid & 31, wrp = tid >> 5;
    unsigned cum = s;
    #pragma unroll
    for (int o = 1; o < 32; o <<= 1) {
        unsigned t = __shfl_up_sync(0xffffffffu, cum, o);
        if (lane >= o) cum += t;
    }
    if (lane == 31) wsum[wrp] = cum;
    __syncthreads();
    if (tid == 0) {
        unsigned acc = 0;
        #pragma unroll
        for (int w = 0; w < 8; w++) { unsigned t = wsum[w]; wsum[w] = acc; acc += t; }
    }
    __syncthreads();
    toff[tid] = wsum[wrp] + cum - s;
    if (tid == 255) toff[256] = M_SAMP;
    __syncthreads();

    const int ranks[4] = {S_LO_A, S_LO_B, S_HI_A, S_HI_B};
    if (tid < 4) {
        unsigned R = (unsigned)ranks[tid];
        int lo = 0, hi = 256;
        while (hi - lo > 1) {
            int mid = (lo + hi) >> 1;
            if (toff[mid] <= R) lo = mid; else hi = mid;
        }
        unsigned acc = toff[lo];
        int bin = lo * 16;
        #pragma unroll
        for (int b = 0; b < 16; b++) {
            unsigned h = hist[lo * 16 + b];
            if (acc + h > R) { bin = lo * 16 + b; break; }
            acc += h;
        }
        sh_bin[tid] = (unsigned)bin;
    }
    __syncthreads();

    if (tid == 0) {
        g_win[slice][0] = funkey(sh_bin[0] << 20);
        g_win[slice][1] = funkey((sh_bin[1] + 1u) << 20);
        g_win[slice][2] = funkey(sh_bin[2] << 20);
        g_win[slice][3] = funkey((sh_bin[3] + 1u) << 20);
        g_cnt[slice][0] = 0;  g_cnt[slice][1] = 0;
        g_ncand[slice][0] = 0; g_ncand[slice][1] = 0;
        g_done[slice] = 0;
        g_flag[slice] = 0;
    }
}

// ============================================================
// Inline select: exact radix-select among candidates of (slice, w)
// Runs on one full block; hist/tsum/red alias gather stash SMEM.
// ============================================================
__device__ void do_select(int slice, int w, unsigned* hist, unsigned* tsum,
                          unsigned* red_u, volatile unsigned* sh2) {
    int tid = threadIdx.x;
    unsigned n = g_ncand[slice][w];
    if (n > CAND_MAX) n = CAND_MAX;
    unsigned cnt = g_cnt[slice][w];

    double pos  = (w == 0) ? 0.01 * (double)(N_PER - 1) : 0.99 * (double)(N_PER - 1);
    long long K = (long long)pos;
    double frac = pos - (double)K;

    if (n < 2) {
        if (tid == 0) g_q[slice][w] = (n == 1) ? g_cand[slice][w][0] : 0.0f;
        return;
    }
    long long rl = K - (long long)cnt;
    if (rl < 0) rl = 0;
    if (rl > (long long)n - 2) rl = (long long)n - 2;
    int r = (int)rl;
    const float* cand = g_cand[slice][w];

    unsigned prefix = 0, pmask = 0;
    int rrem = r;
    const int shifts[3] = {21, 10, 0};
    const int bitsv[3]  = {11, 11, 10};
    #pragma unroll
    for (int p = 0; p < 3; p++) {
        int shift = shifts[p];
        unsigned nb = 1u << bitsv[p];
        unsigned dmask = nb - 1u;
        unsigned per = nb / 256;
        for (unsigned i = tid; i < 2048; i += 256) hist[i] = 0;
        __syncthreads();
        for (unsigned i = tid; i < n; i += 256) {
            unsigned u = fkey(cand[i]);
            if ((u & pmask) == prefix)
                atomicAdd(&hist[(u >> shift) & dmask], 1u);
        }
        __syncthreads();
        unsigned s = 0;
        for (unsigned q2 = 0; q2 < per; q2++) s += hist[tid * per + q2];
        tsum[tid] = s;
        __syncthreads();

        if (tid < 32) {
            unsigned part[8];
            unsigned ls = 0;
            #pragma unroll
            for (int j = 0; j < 8; j++) { part[j] = tsum[tid * 8 + j]; ls += part[j]; }
            unsigned cum = ls;
            #pragma unroll
            for (int o = 1; o < 32; o <<= 1) {
                unsigned t = __shfl_up_sync(0xffffffffu, cum, o);
                if (tid >= o) cum += t;
            }
            unsigned excl = cum - ls;
            unsigned ball = __ballot_sync(0xffffffffu, cum > (unsigned)rrem);
            int cross = __ffs(ball) - 1;
            if (tid == cross) {
                unsigned acc = excl;
                int tc = tid * 8;
                #pragma unroll
                for (int j = 0; j < 8; j++) {
                    if (acc + part[j] > (unsigned)rrem) { tc = tid * 8 + j; break; }
                    acc += part[j];
                }
                unsigned d = (unsigned)tc * per;
                for (unsigned b = 0; b < per; b++) {
                    unsigned h = hist[tc * per + b];
                    if (acc + h > (unsigned)rrem) { d = (unsigned)tc * per + b; break; }
                    acc += h;
                }
                sh2[0] = d;
                sh2[1] = (unsigned)rrem - acc;
            }
        }
        __syncthreads();
        prefix |= sh2[0] << shift;
        pmask  |= dmask << shift;
        rrem = (int)sh2[1];
        __syncthreads();
    }
    unsigned v0key = prefix;

    unsigned cle = 0, mgt = 0xFFFFFFFFu;
    for (unsigned i = tid; i < n; i += 256) {
        unsigned u = fkey(cand[i]);
        cle += (u <= v0key);
        if (u > v0key && u < mgt) mgt = u;
    }
    red_u[tid] = cle; __syncthreads();
    for (int o = 128; o; o >>= 1) {
        if (tid < o) red_u[tid] += red_u[tid + o];
        __syncthreads();
    }
    unsigned cle_tot = red_u[0]; __syncthreads();
    red_u[tid] = mgt; __syncthreads();
    for (int o = 128; o; o >>= 1) {
        if (tid < o) red_u[tid] = (red_u[tid + o] < red_u[tid]) ? red_u[tid + o] : red_u[tid];
        __syncthreads();
    }
    unsigned mgt_tot = red_u[0];
    __syncthreads();

    if (tid == 0) {
        unsigned v1key = (cle_tot >= (unsigned)(r + 2)) ? v0key
                       : ((mgt_tot != 0xFFFFFFFFu) ? mgt_tot : v0key);
        double v0 = (double)funkey(v0key);
        double v1 = (double)funkey(v1key);
        g_q[slice][w] = (float)(v0 + frac * (v1 - v0));
    }
}

// ============================================================
// Mega kernel: ticket-scheduled gather(+select) then normalize.
// Gather tickets [0, GBLK*slices); normalize tickets follow.
// ============================================================
__global__ void __launch_bounds__(256) mega_kernel(const float* __restrict__ x,
                                                   float* __restrict__ out) {
    __shared__ float stL[256 * SROW];        // 9216 B
    __shared__ float stH[256 * SROW];        // 9216 B (aliased in select/fixup)
    __shared__ float ovfL[OVF], ovfH[OVF];
    __shared__ unsigned s_u[16];   // 0:ticket 1:ovl 2:ovh 3:cl 4:ch 5:basel 6:baseh
                                   // 7:totl 8:toth 9:done 10:dig 11:rrem
    __shared__ unsigned wsumL[8], wsumH[8];
    __shared__ float s_q[2];

    int tid = threadIdx.x;
    int lane = tid & 31, wrp = tid >> 5;
    int slices = gridDim.x / (GBLK + NBLKN);
    unsigned gather_total = (unsigned)(GBLK * slices);

    if (tid == 0) {
        s_u[0] = atomicAdd(&g_ticket, 1u);
        s_u[1] = 0; s_u[2] = 0; s_u[3] = 0; s_u[4] = 0;
    }
    __syncthreads();
    unsigned ticket = s_u[0];

    if (ticket < gather_total) {
        // ---------------- gather role ----------------
        int slice = (int)(ticket / GBLK);
        int part  = (int)(ticket % GBLK);

        const float4* xs = (const float4*)(x + (size_t)slice * N_PER
                                             + (size_t)part * GCHUNK);
        float w0 = g_win[slice][0], w1 = g_win[slice][1];
        float w2 = g_win[slice][2], w3 = g_win[slice][3];

        unsigned cl = 0, ch = 0, nl = 0, nh = 0;
        const int NV = GCHUNK / 4;       // 2048
        #pragma unroll 4
        for (int i = tid; i < NV; i += 256) {
            float4 v = xs[i];
            float vv[4] = {v.x, v.y, v.z, v.w};
            #pragma unroll
            for (int c = 0; c < 4; c++) {
                float f = vv[c];
                bool b0 = (f < w0), b2 = (f < w2);
                cl += b0; ch += b2;
                if (!b0 && f < w1) {
                    if (nl < STASH) stL[tid * SROW + nl] = f;
                    else { unsigned o = atomicAdd(&s_u[1], 1u); if (o < OVF) ovfL[o] = f; }
                    nl++;
                }
                if (!b2 && f < w3) {
                    if (nh < STASH) stH[tid * SROW + nh] = f;
                    else { unsigned o = atomicAdd(&s_u[2], 1u); if (o < OVF) ovfH[o] = f; }
                    nh++;
                }
            }
        }
        if (nl > STASH) nl = STASH;
        if (nh > STASH) nh = STASH;

        #pragma unroll
        for (int o = 16; o; o >>= 1) {
            cl += __shfl_down_sync(0xffffffffu, cl, o);
            ch += __shfl_down_sync(0xffffffffu, ch, o);
        }
        if (lane == 0) { atomicAdd(&s_u[3], cl); atomicAdd(&s_u[4], ch); }

        unsigned cumL = nl, cumH = nh;
        #pragma unroll
        for (int o = 1; o < 32; o <<= 1) {
            unsigned tL = __shfl_up_sync(0xffffffffu, cumL, o);
            unsigned tH = __shfl_up_sync(0xffffffffu, cumH, o);
            if (lane >= o) { cumL += tL; cumH += tH; }
        }
        if (lane == 31) { wsumL[wrp] = cumL; wsumH[wrp] = cumH; }
        __syncthreads();

        if (tid == 0) {
            unsigned aL = 0, aH = 0;
            #pragma unroll
            for (int w = 0; w < 8; w++) {
                unsigned tL = wsumL[w], tH = wsumH[w];
                wsumL[w] = aL; wsumH[w] = aH;
                aL += tL; aH += tH;
            }
            unsigned ovl = s_u[1] < OVF ? s_u[1] : OVF;
            unsigned ovh = s_u[2] < OVF ? s_u[2] : OVF;
            s_u[1] = ovl; s_u[2] = ovh;
            s_u[7] = aL; s_u[8] = aH;
            s_u[5] = atomicAdd(&g_ncand[slice][0], aL + ovl);
            s_u[6] = atomicAdd(&g_ncand[slice][1], aH + ovh);
            atomicAdd(&g_cnt[slice][0], s_u[3]);
            atomicAdd(&g_cnt[slice][1], s_u[4]);
        }
        __syncthreads();

        unsigned offL = s_u[5] + wsumL[wrp] + cumL - nl;
        unsigned offH = s_u[6] + wsumH[wrp] + cumH - nh;
        for (unsigned j = 0; j < nl; j++) {
            unsigned gi = offL + j;
            if (gi < CAND_MAX) g_cand[slice][0][gi] = stL[tid * SROW + j];
        }
        for (unsigned j = 0; j < nh; j++) {
            unsigned gi = offH + j;
            if (gi < CAND_MAX) g_cand[slice][1][gi] = stH[tid * SROW + j];
        }
        for (unsigned j = tid; j < s_u[1]; j += 256) {
            unsigned gi = s_u[5] + s_u[7] + j;
            if (gi < CAND_MAX) g_cand[slice][0][gi] = ovfL[j];
        }
        for (unsigned j = tid; j < s_u[2]; j += 256) {
            unsigned gi = s_u[6] + s_u[8] + j;
            if (gi < CAND_MAX) g_cand[slice][1][gi] = ovfH[j];
        }

        // publish + last-block select
        __threadfence();
        __syncthreads();
        if (tid == 0) s_u[9] = atomicAdd(&g_done[slice], 1u);
        __syncthreads();
        if (s_u[9] == GBLK - 1) {
            __threadfence();   // acquire all gather blocks' writes
            unsigned* hist  = (unsigned*)stL;        // 8 KB needed, 9 KB avail
            unsigned* tsum  = (unsigned*)stH;
            unsigned* red_u = (unsigned*)stH + 256;
            do_select(slice, 0, hist, tsum, red_u, &s_u[10]);
            __syncthreads();
            do_select(slice, 1, hist, tsum, red_u, &s_u[10]);
            __threadfence();
            __syncthreads();
            if (tid == 0) atomicExch(&g_flag[slice], 1u);
        }
    } else {
        // ---------------- normalize role ----------------
        unsigned nt = ticket - gather_total;
        int slice = (int)(nt / NBLKN);
        int part  = (int)(nt % NBLKN);

        if (tid == 0) {
            while (atomicAdd(&g_flag[slice], 0u) == 0u) __nanosleep(128);
            __threadfence();
            s_q[0] = __ldcg(&g_q[slice][0]);
            s_q[1] = __ldcg(&g_q[slice][1]);
        }
        __syncthreads();
        float vmin = s_q[0], vmax = s_q[1];
        float a = 1.0f / (vmax - vmin + 1e-8f);
        float b = -vmin * a;

        size_t base = (size_t)slice * N_PER + (size_t)part * NCHUNK;
        const float4* xi = (const float4*)(x + base);
        float4* xo = (float4*)(out + base);
        const int NV = NCHUNK / 4;       // 2048
        #pragma unroll 4
        for (int i = tid; i < NV; i += 256) {
            float4 v = __ldcs(&xi[i]);           // last use: evict-first
            v.x = __saturatef(fmaf(v.x, a, b));
            v.y = __saturatef(fmaf(v.y, a, b));
            v.z = __saturatef(fmaf(v.z, a, b));
            v.w = __saturatef(fmaf(v.w, a, b));
            __stcs(&xo[i], v);                   // streaming store
        }
    }
}

extern "C" void kernel_launch(void* const* d_in, const int* in_sizes, int n_in,
                              void* d_out, int out_size) {
    const float* x = (const float*)d_in[0];
    float* out = (float*)d_out;
    int slices = out_size / N_PER;
    if (slices > MAX_SLICES) slices = MAX_SLICES;
    if (slices < 1) return;

    sample_kernel<<<slices, 256>>>(x);
    mega_kernel<<<slices * (GBLK + NBLKN), 256>>>(x, out);
}